// round 15
// baseline (speedup 1.0000x reference)
#include <cuda_runtime.h>
#include <cstdint>

// ---------------- problem constants (fixed by reference) ----------------
#define NB    16          // batch lines
#define CC    512         // channels (= GEMM K)
#define WW    4096        // max width
#define FD    512         // final dim (= GEMM N)
#define MW    4           // mask width
#define NM    256         // num masks
#define NNEG  10          // num negatives
#define M1    (NM * MW)         // 1024 masked rows
#define M2    (NNEG * NM * MW)  // 10240 negative rows
#define MTOT  (M1 + M2)         // 11264 GEMM rows
#define OUT_REGION0 (NB * CC * WW)   // 33,554,432 floats

// scratch: gathered A rows, PRE-CONVERTED to tf32 bit patterns [MTOT, CC]
__device__ uint32_t g_Ag[(size_t)MTOT * CC];
// scratch: Wq pre-converted to tf32 bit patterns [FD, CC]
__device__ uint32_t g_Bt[(size_t)FD * CC];
// LUT: (n, w) -> mask slot (0..1023) or -1
__device__ short g_lut[NB * WW];

// ---------------------------------------------------------------------------
// Side stream + fork/join events (static init; nothing allocated in-graph)
// ---------------------------------------------------------------------------
static cudaStream_t g_s1 = nullptr;
static cudaEvent_t  g_eFork = nullptr, g_eJoin = nullptr;
static bool         g_ok = false;
namespace {
struct StreamInit {
    StreamInit() {
        g_ok = (cudaStreamCreateWithFlags(&g_s1, cudaStreamNonBlocking) == cudaSuccess)
            && (cudaEventCreateWithFlags(&g_eFork, cudaEventDisableTiming) == cudaSuccess)
            && (cudaEventCreateWithFlags(&g_eJoin, cudaEventDisableTiming) == cudaSuccess);
    }
} g_streamInit;
}

__device__ __forceinline__ uint32_t f2tf(float f) {
    uint32_t r;
    asm("cvt.rna.tf32.f32 %0, %1;\n" : "=r"(r) : "f"(f));
    return r;
}

// ---------------------------------------------------------------------------
// LUT build: clear to -1, then set the 1024 masked (n,w) positions.
// ---------------------------------------------------------------------------
__global__ void k_lut_clear() {
    // 65536 shorts = 8192 int4; 32 blocks x 256 threads x 1 int4
    int i = blockIdx.x * 256 + threadIdx.x;
    ((int4*)g_lut)[i] = make_int4(-1, -1, -1, -1);
}
__global__ void k_lut_set(const int* __restrict__ pack_idx,
                          const int* __restrict__ masked_idx) {
    int i = blockIdx.x * 256 + threadIdx.x;   // 0..M1-1
    int f = __ldg(&pack_idx[__ldg(&masked_idx[i])]);
    int n = f >> 12;
    int w = f & (WW - 1);
    g_lut[n * WW + w] = (short)i;
}

// ---------------------------------------------------------------------------
// K1 (fused): out = masked copy of inputs, with masked (n,w) columns replaced
// by mask_emb rows in-register (no separate scatter kernel, no RMW traffic).
// ---------------------------------------------------------------------------
__global__ void k_copy_fused(const float* __restrict__ in,
                             const int*   __restrict__ seq_len,
                             const float* __restrict__ mask_emb,
                             float*       __restrict__ out) {
    int idx = blockIdx.x * blockDim.x + threadIdx.x;   // NB*CC*WW/4 lanes
    int w   = (idx & (WW / 4 - 1)) << 2;
    int nc  = idx >> 10;                               // n*CC + c
    int n   = nc >> 9;
    int c   = nc & (CC - 1);
    int len = __ldg(&seq_len[n]);
    float4 v = ((const float4*)in)[idx];
    if (w + 3 >= len) {
        if (w + 0 >= len) v.x = 0.f;
        if (w + 1 >= len) v.y = 0.f;
        if (w + 2 >= len) v.z = 0.f;
        v.w = 0.f;
    }
    // mask substitution: LUT entry per (n, w..w+3)
    short4 s = ((const short4*)g_lut)[n * (WW / 4) + (idx & (WW / 4 - 1))];
    int m01 = max((int)s.x, (int)s.y);
    int m23 = max((int)s.z, (int)s.w);
    if (max(m01, m23) >= 0) {   // rare (~1.6% of (n,w) columns)
        if (s.x >= 0) v.x = __ldg(&mask_emb[(s.x & (MW - 1)) * CC + c]);
        if (s.y >= 0) v.y = __ldg(&mask_emb[(s.y & (MW - 1)) * CC + c]);
        if (s.z >= 0) v.z = __ldg(&mask_emb[(s.z & (MW - 1)) * CC + c]);
        if (s.w >= 0) v.w = __ldg(&mask_emb[(s.w & (MW - 1)) * CC + c]);
    }
    ((float4*)out)[idx] = v;
}

// ---------------------------------------------------------------------------
// K3: gather the 11264 packed rows AND convert to tf32 bits (cvt is free here
// — this kernel is scattered-sector-latency bound).
// ---------------------------------------------------------------------------
__global__ void k_gather(const float* __restrict__ in,
                         const int*   __restrict__ pack_idx,
                         const int*   __restrict__ masked_idx,
                         const int*   __restrict__ neg_idx) {
    int r = blockIdx.x;          // 0..MTOT-1
    int c = threadIdx.x;         // 0..CC-1
    int p = (r < M1) ? __ldg(&masked_idx[r]) : __ldg(&neg_idx[r - M1]);
    int f = __ldg(&pack_idx[p]);
    int n = f >> 12;
    int w = f & (WW - 1);
    g_Ag[r * CC + c] = f2tf(__ldg(&in[(n * CC + c) * WW + w]));
}

// Pre-convert Wq [FD, CC] to tf32 bits (1 MB, runs once per launch).
__global__ void k_cvtB(const float* __restrict__ Wq) {
    int i = blockIdx.x * 256 + threadIdx.x;   // FD*CC / 256 = 1024 blocks
    g_Bt[i] = f2tf(__ldg(&Wq[i]));
}

// ---------------------------------------------------------------------------
// K4: D = A @ B^T + bq, tf32 mma.sync, operands PRE-CONVERTED (no cvt in loop)
//   64x128 block tile, BK=16, 8 warps (2Mx4N), warp tile 32x32,
//   double-buffered cp.async, SPAD=20 -> conflict-free fragment LDS.
// ---------------------------------------------------------------------------
#define GBM 64
#define GBN 128
#define GBK 16
#define SPAD 20
#define NSTAGE (CC / GBK)     // 32

__device__ __forceinline__ void cpasync16(void* smem_dst, const void* gsrc) {
    unsigned s = (unsigned)__cvta_generic_to_shared(smem_dst);
    asm volatile("cp.async.cg.shared.global [%0], [%1], 16;\n" :: "r"(s), "l"(gsrc));
}
__device__ __forceinline__ void cpasync_commit() {
    asm volatile("cp.async.commit_group;\n" ::: "memory");
}
template<int N> __device__ __forceinline__ void cpasync_wait() {
    asm volatile("cp.async.wait_group %0;\n" :: "n"(N) : "memory");
}
__device__ __forceinline__ void mma_tf32(float c[4], const uint32_t a[4], const uint32_t b[2]) {
    asm volatile(
        "mma.sync.aligned.m16n8k8.row.col.f32.tf32.tf32.f32 "
        "{%0,%1,%2,%3}, {%4,%5,%6,%7}, {%8,%9}, {%0,%1,%2,%3};\n"
        : "+f"(c[0]), "+f"(c[1]), "+f"(c[2]), "+f"(c[3])
        : "r"(a[0]), "r"(a[1]), "r"(a[2]), "r"(a[3]), "r"(b[0]), "r"(b[1]));
}

__global__ __launch_bounds__(256, 2)
void k_gemm_tf32(const float* __restrict__ bias,   // bq [FD]
                 float*       __restrict__ D) {
    __shared__ uint32_t As[2][GBM][SPAD];   // 64 x 20
    __shared__ uint32_t Bs[2][GBN][SPAD];   // 128 x 20

    const int tid  = threadIdx.x;
    const int bn   = blockIdx.x;         // 0..3
    const int bm   = blockIdx.y;         // 0..175
    const int warp = tid >> 5;
    const int lane = tid & 31;
    const int wm   = warp >> 2;          // 0..1
    const int wn   = warp & 3;           // 0..3
    const int g    = lane >> 2;          // 0..7
    const int t    = lane & 3;           // 0..3

    const int lrow = tid >> 2;           // 0..63
    const int lc4  = (tid & 3) << 2;     // 0,4,8,12
    const uint32_t* Ab  = g_Ag + (size_t)(bm * GBM + lrow) * CC + lc4;
    const uint32_t* Bb0 = g_Bt + (size_t)(bn * GBN + lrow) * CC + lc4;
    const uint32_t* Bb1 = g_Bt + (size_t)(bn * GBN + lrow + 64) * CC + lc4;

    float acc[2][4][4];
#pragma unroll
    for (int mi = 0; mi < 2; mi++)
#pragma unroll
        for (int ni = 0; ni < 4; ni++)
#pragma unroll
            for (int r = 0; r < 4; r++) acc[mi][ni][r] = 0.f;

    cpasync16(&As[0][lrow][lc4],      Ab);
    cpasync16(&Bs[0][lrow][lc4],      Bb0);
    cpasync16(&Bs[0][lrow + 64][lc4], Bb1);
    cpasync_commit();

#pragma unroll 1
    for (int s = 0; s < NSTAGE; ++s) {
        const int buf = s & 1;
        if (s + 1 < NSTAGE) {
            const int k0 = (s + 1) * GBK;
            cpasync16(&As[buf ^ 1][lrow][lc4],      Ab + k0);
            cpasync16(&Bs[buf ^ 1][lrow][lc4],      Bb0 + k0);
            cpasync16(&Bs[buf ^ 1][lrow + 64][lc4], Bb1 + k0);
            cpasync_commit();
            cpasync_wait<1>();
        } else {
            cpasync_wait<0>();
        }
        __syncthreads();

#pragma unroll
        for (int kk = 0; kk < 2; ++kk) {
            const int kb = kk * 8;
            uint32_t a[2][4], bf[4][2];
#pragma unroll
            for (int mi = 0; mi < 2; mi++) {
                const uint32_t* p0 = &As[buf][wm * 32 + mi * 16 + g][kb + t];
                const uint32_t* p1 = &As[buf][wm * 32 + mi * 16 + g + 8][kb + t];
                a[mi][0] = p0[0];
                a[mi][1] = p1[0];
                a[mi][2] = p0[4];
                a[mi][3] = p1[4];
            }
#pragma unroll
            for (int ni = 0; ni < 4; ni++) {
                const uint32_t* p = &Bs[buf][wn * 32 + ni * 8 + g][kb + t];
                bf[ni][0] = p[0];
                bf[ni][1] = p[4];
            }
#pragma unroll
            for (int mi = 0; mi < 2; mi++)
#pragma unroll
                for (int ni = 0; ni < 4; ni++)
                    mma_tf32(acc[mi][ni], a[mi], bf[ni]);
        }
        __syncthreads();
    }

#pragma unroll
    for (int ni = 0; ni < 4; ni++) {
        const int c0 = bn * GBN + wn * 32 + ni * 8 + 2 * t;
        const float b0 = __ldg(&bias[c0]);
        const float b1 = __ldg(&bias[c0 + 1]);
#pragma unroll
        for (int mi = 0; mi < 2; mi++) {
            const int r0 = bm * GBM + wm * 32 + mi * 16 + g;
            float2 v0 = make_float2(acc[mi][ni][0] + b0, acc[mi][ni][1] + b1);
            float2 v1 = make_float2(acc[mi][ni][2] + b0, acc[mi][ni][3] + b1);
            *(float2*)(D + (size_t)r0 * FD + c0)       = v0;
            *(float2*)(D + (size_t)(r0 + 8) * FD + c0) = v1;
        }
    }
}

// ---------------------------------------------------------------------------
// launch: chain A = cvtB, gather -> gemm ; chain B = lut -> fused copy
// ---------------------------------------------------------------------------
extern "C" void kernel_launch(void* const* d_in, const int* in_sizes, int n_in,
                              void* d_out, int out_size) {
    (void)in_sizes; (void)n_in; (void)out_size;
    const float* inputs     = (const float*)d_in[0];
    const int*   seq_len    = (const int*)  d_in[1];
    const int*   pack_idx   = (const int*)  d_in[2];
    const int*   masked_idx = (const int*)  d_in[3];
    const int*   neg_idx    = (const int*)  d_in[4];
    const float* mask_emb   = (const float*)d_in[5];
    const float* Wq         = (const float*)d_in[6];
    const float* bq         = (const float*)d_in[7];
    float* out = (float*)d_out;

    const dim3 gemm_grid(FD / GBN, MTOT / GBM);          // (4, 176)
    const int  copy_blocks = (NB * CC * WW / 4) / 256;   // 32768

    if (g_ok) {
        cudaEventRecord(g_eFork, 0);
        cudaStreamWaitEvent(g_s1, g_eFork, 0);

        // chain B (side stream): LUT build, then fused masked copy
        k_lut_clear<<<32, 256, 0, g_s1>>>();
        k_lut_set<<<M1 / 256, 256, 0, g_s1>>>(pack_idx, masked_idx);
        k_copy_fused<<<copy_blocks, 256, 0, g_s1>>>(inputs, seq_len, mask_emb, out);

        // chain A (main stream): pre-convert B, gather+convert A, GEMM
        k_cvtB<<<FD * CC / 256, 256>>>(Wq);
        k_gather<<<MTOT, CC>>>(inputs, pack_idx, masked_idx, neg_idx);
        k_gemm_tf32<<<gemm_grid, 256>>>(bq, out + OUT_REGION0);

        cudaEventRecord(g_eJoin, g_s1);
        cudaStreamWaitEvent(0, g_eJoin, 0);
    } else {
        k_cvtB<<<FD * CC / 256, 256>>>(Wq);
        k_gather<<<MTOT, CC>>>(inputs, pack_idx, masked_idx, neg_idx);
        k_gemm_tf32<<<gemm_grid, 256>>>(bq, out + OUT_REGION0);
        k_lut_clear<<<32, 256>>>();
        k_lut_set<<<M1 / 256, 256>>>(pack_idx, masked_idx);
        k_copy_fused<<<copy_blocks, 256>>>(inputs, seq_len, mask_emb, out);
    }
}

// round 16
// speedup vs baseline: 1.0002x; 1.0002x over previous
#include <cuda_runtime.h>
#include <cstdint>

// ---------------- problem constants (fixed by reference) ----------------
#define NB    16          // batch lines
#define CC    512         // channels (= GEMM K)
#define WW    4096        // max width
#define FD    512         // final dim (= GEMM N)
#define MW    4           // mask width
#define NM    256         // num masks
#define NNEG  10          // num negatives
#define M1    (NM * MW)         // 1024 masked rows
#define M2    (NNEG * NM * MW)  // 10240 negative rows
#define MTOT  (M1 + M2)         // 11264 GEMM rows
#define OUT_REGION0 (NB * CC * WW)   // 33,554,432 floats

// scratch: gathered A rows, PRE-CONVERTED to tf32 bit patterns [MTOT, CC]
__device__ uint32_t g_Ag[(size_t)MTOT * CC];
// scratch: Wq pre-converted to tf32 bit patterns [FD, CC]
__device__ uint32_t g_Bt[(size_t)FD * CC];
// LUT: (n, w) -> mask slot (0..1023) or -1
__device__ short g_lut[NB * WW];

// ---------------------------------------------------------------------------
// Side stream + fork/join events (static init; nothing allocated in-graph)
// ---------------------------------------------------------------------------
static cudaStream_t g_s1 = nullptr;
static cudaEvent_t  g_eFork = nullptr, g_eJoin = nullptr;
static bool         g_ok = false;
namespace {
struct StreamInit {
    StreamInit() {
        g_ok = (cudaStreamCreateWithFlags(&g_s1, cudaStreamNonBlocking) == cudaSuccess)
            && (cudaEventCreateWithFlags(&g_eFork, cudaEventDisableTiming) == cudaSuccess)
            && (cudaEventCreateWithFlags(&g_eJoin, cudaEventDisableTiming) == cudaSuccess);
    }
} g_streamInit;
}

__device__ __forceinline__ uint32_t f2tf(float f) {
    uint32_t r;
    asm("cvt.rna.tf32.f32 %0, %1;\n" : "=r"(r) : "f"(f));
    return r;
}

// ---------------------------------------------------------------------------
// LUT build: clear to -1, then set the 1024 masked (n,w) positions.
// ---------------------------------------------------------------------------
__global__ void k_lut_clear() {
    // 65536 shorts = 8192 int4; 32 blocks x 256 threads x 1 int4
    int i = blockIdx.x * 256 + threadIdx.x;
    ((int4*)g_lut)[i] = make_int4(-1, -1, -1, -1);
}
__global__ void k_lut_set(const int* __restrict__ pack_idx,
                          const int* __restrict__ masked_idx) {
    int i = blockIdx.x * 256 + threadIdx.x;   // 0..M1-1
    int f = __ldg(&pack_idx[__ldg(&masked_idx[i])]);
    int n = f >> 12;
    int w = f & (WW - 1);
    g_lut[n * WW + w] = (short)i;
}

// ---------------------------------------------------------------------------
// K1 (fused): out = masked copy of inputs, with masked (n,w) columns replaced
// by mask_emb rows in-register (no separate scatter kernel, no RMW traffic).
// ---------------------------------------------------------------------------
__global__ void k_copy_fused(const float* __restrict__ in,
                             const int*   __restrict__ seq_len,
                             const float* __restrict__ mask_emb,
                             float*       __restrict__ out) {
    int idx = blockIdx.x * blockDim.x + threadIdx.x;   // NB*CC*WW/4 lanes
    int w   = (idx & (WW / 4 - 1)) << 2;
    int nc  = idx >> 10;                               // n*CC + c
    int n   = nc >> 9;
    int c   = nc & (CC - 1);
    int len = __ldg(&seq_len[n]);
    float4 v = ((const float4*)in)[idx];
    if (w + 3 >= len) {
        if (w + 0 >= len) v.x = 0.f;
        if (w + 1 >= len) v.y = 0.f;
        if (w + 2 >= len) v.z = 0.f;
        v.w = 0.f;
    }
    // mask substitution: LUT entry per (n, w..w+3)
    short4 s = ((const short4*)g_lut)[n * (WW / 4) + (idx & (WW / 4 - 1))];
    int m01 = max((int)s.x, (int)s.y);
    int m23 = max((int)s.z, (int)s.w);
    if (max(m01, m23) >= 0) {   // rare (~1.6% of (n,w) columns)
        if (s.x >= 0) v.x = __ldg(&mask_emb[(s.x & (MW - 1)) * CC + c]);
        if (s.y >= 0) v.y = __ldg(&mask_emb[(s.y & (MW - 1)) * CC + c]);
        if (s.z >= 0) v.z = __ldg(&mask_emb[(s.z & (MW - 1)) * CC + c]);
        if (s.w >= 0) v.w = __ldg(&mask_emb[(s.w & (MW - 1)) * CC + c]);
    }
    ((float4*)out)[idx] = v;
}

// ---------------------------------------------------------------------------
// K3: gather the 11264 packed rows AND convert to tf32 bits (cvt is free here
// — this kernel is scattered-sector-latency bound).
// ---------------------------------------------------------------------------
__global__ void k_gather(const float* __restrict__ in,
                         const int*   __restrict__ pack_idx,
                         const int*   __restrict__ masked_idx,
                         const int*   __restrict__ neg_idx) {
    int r = blockIdx.x;          // 0..MTOT-1
    int c = threadIdx.x;         // 0..CC-1
    int p = (r < M1) ? __ldg(&masked_idx[r]) : __ldg(&neg_idx[r - M1]);
    int f = __ldg(&pack_idx[p]);
    int n = f >> 12;
    int w = f & (WW - 1);
    g_Ag[r * CC + c] = f2tf(__ldg(&in[(n * CC + c) * WW + w]));
}

// Pre-convert Wq [FD, CC] to tf32 bits (1 MB, runs once per launch).
__global__ void k_cvtB(const float* __restrict__ Wq) {
    int i = blockIdx.x * 256 + threadIdx.x;   // FD*CC / 256 = 1024 blocks
    g_Bt[i] = f2tf(__ldg(&Wq[i]));
}

// ---------------------------------------------------------------------------
// K4: D = A @ B^T + bq, tf32 mma.sync, operands PRE-CONVERTED (no cvt in loop)
//   64x128 block tile, BK=16, 8 warps (2Mx4N), warp tile 32x32,
//   double-buffered cp.async, SPAD=20 -> conflict-free fragment LDS.
// ---------------------------------------------------------------------------
#define GBM 64
#define GBN 128
#define GBK 16
#define SPAD 20
#define NSTAGE (CC / GBK)     // 32

__device__ __forceinline__ void cpasync16(void* smem_dst, const void* gsrc) {
    unsigned s = (unsigned)__cvta_generic_to_shared(smem_dst);
    asm volatile("cp.async.cg.shared.global [%0], [%1], 16;\n" :: "r"(s), "l"(gsrc));
}
__device__ __forceinline__ void cpasync_commit() {
    asm volatile("cp.async.commit_group;\n" ::: "memory");
}
template<int N> __device__ __forceinline__ void cpasync_wait() {
    asm volatile("cp.async.wait_group %0;\n" :: "n"(N) : "memory");
}
__device__ __forceinline__ void mma_tf32(float c[4], const uint32_t a[4], const uint32_t b[2]) {
    asm volatile(
        "mma.sync.aligned.m16n8k8.row.col.f32.tf32.tf32.f32 "
        "{%0,%1,%2,%3}, {%4,%5,%6,%7}, {%8,%9}, {%0,%1,%2,%3};\n"
        : "+f"(c[0]), "+f"(c[1]), "+f"(c[2]), "+f"(c[3])
        : "r"(a[0]), "r"(a[1]), "r"(a[2]), "r"(a[3]), "r"(b[0]), "r"(b[1]));
}

__global__ __launch_bounds__(256, 2)
void k_gemm_tf32(const float* __restrict__ bias,   // bq [FD]
                 float*       __restrict__ D) {
    __shared__ uint32_t As[2][GBM][SPAD];   // 64 x 20
    __shared__ uint32_t Bs[2][GBN][SPAD];   // 128 x 20

    const int tid  = threadIdx.x;
    const int bn   = blockIdx.x;         // 0..3
    const int bm   = blockIdx.y;         // 0..175
    const int warp = tid >> 5;
    const int lane = tid & 31;
    const int wm   = warp >> 2;          // 0..1
    const int wn   = warp & 3;           // 0..3
    const int g    = lane >> 2;          // 0..7
    const int t    = lane & 3;           // 0..3

    const int lrow = tid >> 2;           // 0..63
    const int lc4  = (tid & 3) << 2;     // 0,4,8,12
    const uint32_t* Ab  = g_Ag + (size_t)(bm * GBM + lrow) * CC + lc4;
    const uint32_t* Bb0 = g_Bt + (size_t)(bn * GBN + lrow) * CC + lc4;
    const uint32_t* Bb1 = g_Bt + (size_t)(bn * GBN + lrow + 64) * CC + lc4;

    float acc[2][4][4];
#pragma unroll
    for (int mi = 0; mi < 2; mi++)
#pragma unroll
        for (int ni = 0; ni < 4; ni++)
#pragma unroll
            for (int r = 0; r < 4; r++) acc[mi][ni][r] = 0.f;

    cpasync16(&As[0][lrow][lc4],      Ab);
    cpasync16(&Bs[0][lrow][lc4],      Bb0);
    cpasync16(&Bs[0][lrow + 64][lc4], Bb1);
    cpasync_commit();

#pragma unroll 1
    for (int s = 0; s < NSTAGE; ++s) {
        const int buf = s & 1;
        if (s + 1 < NSTAGE) {
            const int k0 = (s + 1) * GBK;
            cpasync16(&As[buf ^ 1][lrow][lc4],      Ab + k0);
            cpasync16(&Bs[buf ^ 1][lrow][lc4],      Bb0 + k0);
            cpasync16(&Bs[buf ^ 1][lrow + 64][lc4], Bb1 + k0);
            cpasync_commit();
            cpasync_wait<1>();
        } else {
            cpasync_wait<0>();
        }
        __syncthreads();

#pragma unroll
        for (int kk = 0; kk < 2; ++kk) {
            const int kb = kk * 8;
            uint32_t a[2][4], bf[4][2];
#pragma unroll
            for (int mi = 0; mi < 2; mi++) {
                const uint32_t* p0 = &As[buf][wm * 32 + mi * 16 + g][kb + t];
                const uint32_t* p1 = &As[buf][wm * 32 + mi * 16 + g + 8][kb + t];
                a[mi][0] = p0[0];
                a[mi][1] = p1[0];
                a[mi][2] = p0[4];
                a[mi][3] = p1[4];
            }
#pragma unroll
            for (int ni = 0; ni < 4; ni++) {
                const uint32_t* p = &Bs[buf][wn * 32 + ni * 8 + g][kb + t];
                bf[ni][0] = p[0];
                bf[ni][1] = p[4];
            }
#pragma unroll
            for (int mi = 0; mi < 2; mi++)
#pragma unroll
                for (int ni = 0; ni < 4; ni++)
                    mma_tf32(acc[mi][ni], a[mi], bf[ni]);
        }
        __syncthreads();
    }

#pragma unroll
    for (int ni = 0; ni < 4; ni++) {
        const int c0 = bn * GBN + wn * 32 + ni * 8 + 2 * t;
        const float b0 = __ldg(&bias[c0]);
        const float b1 = __ldg(&bias[c0 + 1]);
#pragma unroll
        for (int mi = 0; mi < 2; mi++) {
            const int r0 = bm * GBM + wm * 32 + mi * 16 + g;
            float2 v0 = make_float2(acc[mi][ni][0] + b0, acc[mi][ni][1] + b1);
            float2 v1 = make_float2(acc[mi][ni][2] + b0, acc[mi][ni][3] + b1);
            *(float2*)(D + (size_t)r0 * FD + c0)       = v0;
            *(float2*)(D + (size_t)(r0 + 8) * FD + c0) = v1;
        }
    }
}

// ---------------------------------------------------------------------------
// launch: chain A = cvtB, gather -> gemm ; chain B = lut -> fused copy
// ---------------------------------------------------------------------------
extern "C" void kernel_launch(void* const* d_in, const int* in_sizes, int n_in,
                              void* d_out, int out_size) {
    (void)in_sizes; (void)n_in; (void)out_size;
    const float* inputs     = (const float*)d_in[0];
    const int*   seq_len    = (const int*)  d_in[1];
    const int*   pack_idx   = (const int*)  d_in[2];
    const int*   masked_idx = (const int*)  d_in[3];
    const int*   neg_idx    = (const int*)  d_in[4];
    const float* mask_emb   = (const float*)d_in[5];
    const float* Wq         = (const float*)d_in[6];
    const float* bq         = (const float*)d_in[7];
    float* out = (float*)d_out;

    const dim3 gemm_grid(FD / GBN, MTOT / GBM);          // (4, 176)
    const int  copy_blocks = (NB * CC * WW / 4) / 256;   // 32768

    if (g_ok) {
        cudaEventRecord(g_eFork, 0);
        cudaStreamWaitEvent(g_s1, g_eFork, 0);

        // chain B (side stream): LUT build, then fused masked copy
        k_lut_clear<<<32, 256, 0, g_s1>>>();
        k_lut_set<<<M1 / 256, 256, 0, g_s1>>>(pack_idx, masked_idx);
        k_copy_fused<<<copy_blocks, 256, 0, g_s1>>>(inputs, seq_len, mask_emb, out);

        // chain A (main stream): pre-convert B, gather+convert A, GEMM
        k_cvtB<<<FD * CC / 256, 256>>>(Wq);
        k_gather<<<MTOT, CC>>>(inputs, pack_idx, masked_idx, neg_idx);
        k_gemm_tf32<<<gemm_grid, 256>>>(bq, out + OUT_REGION0);

        cudaEventRecord(g_eJoin, g_s1);
        cudaStreamWaitEvent(0, g_eJoin, 0);
    } else {
        k_cvtB<<<FD * CC / 256, 256>>>(Wq);
        k_gather<<<MTOT, CC>>>(inputs, pack_idx, masked_idx, neg_idx);
        k_gemm_tf32<<<gemm_grid, 256>>>(bq, out + OUT_REGION0);
        k_lut_clear<<<32, 256>>>();
        k_lut_set<<<M1 / 256, 256>>>(pack_idx, masked_idx);
        k_copy_fused<<<copy_blocks, 256>>>(inputs, seq_len, mask_emb, out);
    }
}

// round 17
// speedup vs baseline: 1.0020x; 1.0018x over previous
#include <cuda_runtime.h>
#include <cstdint>

// ---------------- problem constants (fixed by reference) ----------------
#define NB    16          // batch lines
#define CC    512         // channels (= GEMM K)
#define WW    4096        // max width
#define FD    512         // final dim (= GEMM N)
#define MW    4           // mask width
#define NM    256         // num masks
#define NNEG  10          // num negatives
#define M1    (NM * MW)         // 1024 masked rows
#define M2    (NNEG * NM * MW)  // 10240 negative rows
#define MTOT  (M1 + M2)         // 11264 GEMM rows
#define OUT_REGION0 (NB * CC * WW)   // 33,554,432 floats

// scratch: gathered A rows, PRE-CONVERTED to tf32 bit patterns [MTOT, CC]
__device__ uint32_t g_Ag[(size_t)MTOT * CC];
// scratch: Wq pre-converted to tf32 bit patterns [FD, CC]
__device__ uint32_t g_Bt[(size_t)FD * CC];
// nibble mask: 4 bits per (n,w): 0 = unmasked, else mask_emb row + 1.
// word = g_nib[n*512 + (w>>3)], nibble = (w & 7).  Total 32 KB (L1/L2 resident).
__device__ uint32_t g_nib[NB * WW / 8];

// ---------------------------------------------------------------------------
// Side stream + fork/join events (static init; nothing allocated in-graph)
// ---------------------------------------------------------------------------
static cudaStream_t g_s1 = nullptr;
static cudaEvent_t  g_eFork = nullptr, g_eJoin = nullptr;
static bool         g_ok = false;
namespace {
struct StreamInit {
    StreamInit() {
        g_ok = (cudaStreamCreateWithFlags(&g_s1, cudaStreamNonBlocking) == cudaSuccess)
            && (cudaEventCreateWithFlags(&g_eFork, cudaEventDisableTiming) == cudaSuccess)
            && (cudaEventCreateWithFlags(&g_eJoin, cudaEventDisableTiming) == cudaSuccess);
    }
} g_streamInit;
}

__device__ __forceinline__ uint32_t f2tf(float f) {
    uint32_t r;
    asm("cvt.rna.tf32.f32 %0, %1;\n" : "=r"(r) : "f"(f));
    return r;
}

// ---------------------------------------------------------------------------
// nibble-mask build: clear 32KB, then atomicOr the 1024 masked positions.
// (masked blocks are non-overlapping, so OR never collides within a nibble)
// ---------------------------------------------------------------------------
__global__ void k_nib_clear() {
    // 8192 words = 2048 int4; 8 blocks x 256 threads
    int i = blockIdx.x * 256 + threadIdx.x;
    ((int4*)g_nib)[i] = make_int4(0, 0, 0, 0);
}
__global__ void k_nib_set(const int* __restrict__ pack_idx,
                          const int* __restrict__ masked_idx) {
    int i = blockIdx.x * 256 + threadIdx.x;   // 0..M1-1
    int f = __ldg(&pack_idx[__ldg(&masked_idx[i])]);
    int n = f >> 12;
    int w = f & (WW - 1);
    uint32_t val = (uint32_t)((i & (MW - 1)) + 1) << ((w & 7) * 4);
    atomicOr(&g_nib[n * (WW / 8) + (w >> 3)], val);
}

// ---------------------------------------------------------------------------
// K1 (fused): out = length-masked copy of inputs, with masked (n,w) columns
// replaced by mask_emb rows in-register. Nibble lookup costs 4B per 2 threads
// (L1-resident) instead of the 8B/thread LUT that regressed R16.
// ---------------------------------------------------------------------------
__global__ void k_copy_fused(const float* __restrict__ in,
                             const int*   __restrict__ seq_len,
                             const float* __restrict__ mask_emb,
                             float*       __restrict__ out) {
    int idx = blockIdx.x * blockDim.x + threadIdx.x;   // NB*CC*WW/4 lanes
    int q   = idx & (WW / 4 - 1);                      // w4 index, 0..1023
    int w   = q << 2;
    int nc  = idx >> 10;                               // n*CC + c
    int n   = nc >> 9;
    int c   = nc & (CC - 1);
    int len = __ldg(&seq_len[n]);
    float4 v = ((const float4*)in)[idx];
    if (w + 3 >= len) {
        if (w + 0 >= len) v.x = 0.f;
        if (w + 1 >= len) v.y = 0.f;
        if (w + 2 >= len) v.z = 0.f;
        v.w = 0.f;
    }
    // 16 bits covering w..w+3 (two threads share each uint32 word)
    const uint32_t* nibp = g_nib;
    uint32_t word = __ldg(&nibp[n * (WW / 8) + (q >> 1)]);
    uint32_t bits = (word >> ((q & 1) * 16)) & 0xFFFFu;
    if (bits) {                                        // rare (~1.6% of columns)
        uint32_t b0 = bits & 15u, b1 = (bits >> 4) & 15u;
        uint32_t b2 = (bits >> 8) & 15u, b3 = (bits >> 12) & 15u;
        if (b0) v.x = __ldg(&mask_emb[(b0 - 1) * CC + c]);
        if (b1) v.y = __ldg(&mask_emb[(b1 - 1) * CC + c]);
        if (b2) v.z = __ldg(&mask_emb[(b2 - 1) * CC + c]);
        if (b3) v.w = __ldg(&mask_emb[(b3 - 1) * CC + c]);
    }
    ((float4*)out)[idx] = v;
}

// ---------------------------------------------------------------------------
// K3: gather the 11264 packed rows AND convert to tf32 bits (cvt is free here
// — this kernel is scattered-sector-latency bound).
// ---------------------------------------------------------------------------
__global__ void k_gather(const float* __restrict__ in,
                         const int*   __restrict__ pack_idx,
                         const int*   __restrict__ masked_idx,
                         const int*   __restrict__ neg_idx) {
    int r = blockIdx.x;          // 0..MTOT-1
    int c = threadIdx.x;         // 0..CC-1
    int p = (r < M1) ? __ldg(&masked_idx[r]) : __ldg(&neg_idx[r - M1]);
    int f = __ldg(&pack_idx[p]);
    int n = f >> 12;
    int w = f & (WW - 1);
    g_Ag[r * CC + c] = f2tf(__ldg(&in[(n * CC + c) * WW + w]));
}

// Pre-convert Wq [FD, CC] to tf32 bits (1 MB, runs once per launch).
__global__ void k_cvtB(const float* __restrict__ Wq) {
    int i = blockIdx.x * 256 + threadIdx.x;   // FD*CC / 256 = 1024 blocks
    g_Bt[i] = f2tf(__ldg(&Wq[i]));
}

// ---------------------------------------------------------------------------
// K4: D = A @ B^T + bq, tf32 mma.sync, operands PRE-CONVERTED (no cvt in loop)
//   64x128 block tile, BK=16, 8 warps (2Mx4N), warp tile 32x32,
//   double-buffered cp.async, SPAD=20 -> conflict-free fragment LDS.
// ---------------------------------------------------------------------------
#define GBM 64
#define GBN 128
#define GBK 16
#define SPAD 20
#define NSTAGE (CC / GBK)     // 32

__device__ __forceinline__ void cpasync16(void* smem_dst, const void* gsrc) {
    unsigned s = (unsigned)__cvta_generic_to_shared(smem_dst);
    asm volatile("cp.async.cg.shared.global [%0], [%1], 16;\n" :: "r"(s), "l"(gsrc));
}
__device__ __forceinline__ void cpasync_commit() {
    asm volatile("cp.async.commit_group;\n" ::: "memory");
}
template<int N> __device__ __forceinline__ void cpasync_wait() {
    asm volatile("cp.async.wait_group %0;\n" :: "n"(N) : "memory");
}
__device__ __forceinline__ void mma_tf32(float c[4], const uint32_t a[4], const uint32_t b[2]) {
    asm volatile(
        "mma.sync.aligned.m16n8k8.row.col.f32.tf32.tf32.f32 "
        "{%0,%1,%2,%3}, {%4,%5,%6,%7}, {%8,%9}, {%0,%1,%2,%3};\n"
        : "+f"(c[0]), "+f"(c[1]), "+f"(c[2]), "+f"(c[3])
        : "r"(a[0]), "r"(a[1]), "r"(a[2]), "r"(a[3]), "r"(b[0]), "r"(b[1]));
}

__global__ __launch_bounds__(256, 2)
void k_gemm_tf32(const float* __restrict__ bias,   // bq [FD]
                 float*       __restrict__ D) {
    __shared__ uint32_t As[2][GBM][SPAD];   // 64 x 20
    __shared__ uint32_t Bs[2][GBN][SPAD];   // 128 x 20

    const int tid  = threadIdx.x;
    const int bn   = blockIdx.x;         // 0..3
    const int bm   = blockIdx.y;         // 0..175
    const int warp = tid >> 5;
    const int lane = tid & 31;
    const int wm   = warp >> 2;          // 0..1
    const int wn   = warp & 3;           // 0..3
    const int g    = lane >> 2;          // 0..7
    const int t    = lane & 3;           // 0..3

    const int lrow = tid >> 2;           // 0..63
    const int lc4  = (tid & 3) << 2;     // 0,4,8,12
    const uint32_t* Ab  = g_Ag + (size_t)(bm * GBM + lrow) * CC + lc4;
    const uint32_t* Bb0 = g_Bt + (size_t)(bn * GBN + lrow) * CC + lc4;
    const uint32_t* Bb1 = g_Bt + (size_t)(bn * GBN + lrow + 64) * CC + lc4;

    float acc[2][4][4];
#pragma unroll
    for (int mi = 0; mi < 2; mi++)
#pragma unroll
        for (int ni = 0; ni < 4; ni++)
#pragma unroll
            for (int r = 0; r < 4; r++) acc[mi][ni][r] = 0.f;

    cpasync16(&As[0][lrow][lc4],      Ab);
    cpasync16(&Bs[0][lrow][lc4],      Bb0);
    cpasync16(&Bs[0][lrow + 64][lc4], Bb1);
    cpasync_commit();

#pragma unroll 1
    for (int s = 0; s < NSTAGE; ++s) {
        const int buf = s & 1;
        if (s + 1 < NSTAGE) {
            const int k0 = (s + 1) * GBK;
            cpasync16(&As[buf ^ 1][lrow][lc4],      Ab + k0);
            cpasync16(&Bs[buf ^ 1][lrow][lc4],      Bb0 + k0);
            cpasync16(&Bs[buf ^ 1][lrow + 64][lc4], Bb1 + k0);
            cpasync_commit();
            cpasync_wait<1>();
        } else {
            cpasync_wait<0>();
        }
        __syncthreads();

#pragma unroll
        for (int kk = 0; kk < 2; ++kk) {
            const int kb = kk * 8;
            uint32_t a[2][4], bf[4][2];
#pragma unroll
            for (int mi = 0; mi < 2; mi++) {
                const uint32_t* p0 = &As[buf][wm * 32 + mi * 16 + g][kb + t];
                const uint32_t* p1 = &As[buf][wm * 32 + mi * 16 + g + 8][kb + t];
                a[mi][0] = p0[0];
                a[mi][1] = p1[0];
                a[mi][2] = p0[4];
                a[mi][3] = p1[4];
            }
#pragma unroll
            for (int ni = 0; ni < 4; ni++) {
                const uint32_t* p = &Bs[buf][wn * 32 + ni * 8 + g][kb + t];
                bf[ni][0] = p[0];
                bf[ni][1] = p[4];
            }
#pragma unroll
            for (int mi = 0; mi < 2; mi++)
#pragma unroll
                for (int ni = 0; ni < 4; ni++)
                    mma_tf32(acc[mi][ni], a[mi], bf[ni]);
        }
        __syncthreads();
    }

#pragma unroll
    for (int ni = 0; ni < 4; ni++) {
        const int c0 = bn * GBN + wn * 32 + ni * 8 + 2 * t;
        const float b0 = __ldg(&bias[c0]);
        const float b1 = __ldg(&bias[c0 + 1]);
#pragma unroll
        for (int mi = 0; mi < 2; mi++) {
            const int r0 = bm * GBM + wm * 32 + mi * 16 + g;
            float2 v0 = make_float2(acc[mi][ni][0] + b0, acc[mi][ni][1] + b1);
            float2 v1 = make_float2(acc[mi][ni][2] + b0, acc[mi][ni][3] + b1);
            *(float2*)(D + (size_t)r0 * FD + c0)       = v0;
            *(float2*)(D + (size_t)(r0 + 8) * FD + c0) = v1;
        }
    }
}

// ---------------------------------------------------------------------------
// launch: chain A = cvtB, gather -> gemm ; chain B = nib -> fused copy
// ---------------------------------------------------------------------------
extern "C" void kernel_launch(void* const* d_in, const int* in_sizes, int n_in,
                              void* d_out, int out_size) {
    (void)in_sizes; (void)n_in; (void)out_size;
    const float* inputs     = (const float*)d_in[0];
    const int*   seq_len    = (const int*)  d_in[1];
    const int*   pack_idx   = (const int*)  d_in[2];
    const int*   masked_idx = (const int*)  d_in[3];
    const int*   neg_idx    = (const int*)  d_in[4];
    const float* mask_emb   = (const float*)d_in[5];
    const float* Wq         = (const float*)d_in[6];
    const float* bq         = (const float*)d_in[7];
    float* out = (float*)d_out;

    const dim3 gemm_grid(FD / GBN, MTOT / GBM);          // (4, 176)
    const int  copy_blocks = (NB * CC * WW / 4) / 256;   // 32768

    if (g_ok) {
        cudaEventRecord(g_eFork, 0);
        cudaStreamWaitEvent(g_s1, g_eFork, 0);

        // chain B (side stream): nibble mask build, then fused masked copy
        k_nib_clear<<<8, 256, 0, g_s1>>>();
        k_nib_set<<<M1 / 256, 256, 0, g_s1>>>(pack_idx, masked_idx);
        k_copy_fused<<<copy_blocks, 256, 0, g_s1>>>(inputs, seq_len, mask_emb, out);

        // chain A (main stream): pre-convert B, gather+convert A, GEMM
        k_cvtB<<<FD * CC / 256, 256>>>(Wq);
        k_gather<<<MTOT, CC>>>(inputs, pack_idx, masked_idx, neg_idx);
        k_gemm_tf32<<<gemm_grid, 256>>>(bq, out + OUT_REGION0);

        cudaEventRecord(g_eJoin, g_s1);
        cudaStreamWaitEvent(0, g_eJoin, 0);
    } else {
        k_cvtB<<<FD * CC / 256, 256>>>(Wq);
        k_gather<<<MTOT, CC>>>(inputs, pack_idx, masked_idx, neg_idx);
        k_gemm_tf32<<<gemm_grid, 256>>>(bq, out + OUT_REGION0);
        k_nib_clear<<<8, 256>>>();
        k_nib_set<<<M1 / 256, 256>>>(pack_idx, masked_idx);
        k_copy_fused<<<copy_blocks, 256>>>(inputs, seq_len, mask_emb, out);
    }
}